// round 1
// baseline (speedup 1.0000x reference)
#include <cuda_runtime.h>
#include <cstdint>

// Problem constants (from reference):
//   x: (16, 3, 256, 256) f32  -- only channel 0 used
//   w: (64, 3, 3, 3)     f32  -- only w[:, 2, :, :] used
//   b: (64,)             f32
//   out: (16, 64, 254, 254) f32  (valid 3x3 conv of x[:,0] with w[:,2])
#define NB    16
#define F_OUT 64
#define Hh    256
#define Ww    256
#define HO    254
#define WO    254
#define IP    (HO / 2)   // 127 row-pairs
#define JP    (WO / 2)   // 127 col-pairs

// packed f32x2 FMA (Blackwell): d = a * w + c on both lanes
static __device__ __forceinline__ unsigned long long ffma2(
    unsigned long long a, unsigned long long w, unsigned long long c) {
    unsigned long long d;
    asm("fma.rn.f32x2 %0, %1, %2, %3;" : "=l"(d) : "l"(a), "l"(w), "l"(c));
    return d;
}

static __device__ __forceinline__ unsigned long long pack2(float lo, float hi) {
    unsigned long long d;
    asm("mov.b64 %0, {%1, %2};" : "=l"(d) : "f"(lo), "f"(hi));
    return d;
}

__global__ __launch_bounds__(256) void conv2dcq_kernel(
    const float* __restrict__ x,
    const float* __restrict__ w,
    const float* __restrict__ bias,
    float* __restrict__ out) {

    // Weights duplicated to (w, w) f32x2 in smem; bias likewise.
    __shared__ unsigned long long sw[F_OUT * 9];
    __shared__ unsigned long long sb[F_OUT];

    const int tid = threadIdx.x;
    for (int t = tid; t < F_OUT * 9; t += blockDim.x) {
        const int f = t / 9;
        const int k = t % 9;
        const float v = w[f * 27 + 18 + k];   // w[f, 2, a, b]
        sw[t] = pack2(v, v);
    }
    if (tid < F_OUT) {
        const float v = bias[tid];
        sb[tid] = pack2(v, v);
    }
    __syncthreads();

    const int idx = blockIdx.x * blockDim.x + tid;
    if (idx >= NB * IP * JP) return;

    const int jp = idx % JP;
    const int t2 = idx / JP;
    const int ip = t2 % IP;
    const int n  = t2 / IP;
    const int i  = ip * 2;
    const int j  = jp * 2;

    // Input channel 0 base: 4 rows x 4 cols needed for a 2x2 output patch.
    const float* xb = x + (size_t)n * 3 * Hh * Ww + (size_t)i * Ww + j;

    // P[r][b] = (x[i+r][j+b], x[i+r][j+b+1]) packed f32x2, r=0..3, b=0..2
    unsigned long long P[4][3];
    #pragma unroll
    for (int r = 0; r < 4; r++) {
        // j is even -> 8B-aligned float2 loads
        const float2 lo = *reinterpret_cast<const float2*>(xb + (size_t)r * Ww);
        const float2 hi = *reinterpret_cast<const float2*>(xb + (size_t)r * Ww + 2);
        P[r][0] = pack2(lo.x, lo.y);
        P[r][1] = pack2(lo.y, hi.x);
        P[r][2] = pack2(hi.x, hi.y);
    }

    float* ob = out + (size_t)n * F_OUT * HO * WO + (size_t)i * WO + j;

    #pragma unroll 4
    for (int f = 0; f < F_OUT; f++) {
        unsigned long long a0 = sb[f];
        unsigned long long a1 = a0;
        const unsigned long long* wf = &sw[f * 9];
        #pragma unroll
        for (int a = 0; a < 3; a++) {
            #pragma unroll
            for (int b = 0; b < 3; b++) {
                const unsigned long long wv = wf[a * 3 + b];  // LDS.64 broadcast
                a0 = ffma2(P[a][b],     wv, a0);
                a1 = ffma2(P[a + 1][b], wv, a1);
            }
        }
        // 8B-aligned stores: row stride 254*4 = 1016 B (8B multiple), j even
        *reinterpret_cast<unsigned long long*>(ob)      = a0;
        *reinterpret_cast<unsigned long long*>(ob + WO) = a1;
        ob += (size_t)HO * WO;
    }
}

extern "C" void kernel_launch(void* const* d_in, const int* in_sizes, int n_in,
                              void* d_out, int out_size) {
    const float* x    = (const float*)d_in[0];
    const float* w    = (const float*)d_in[1];
    const float* bias = (const float*)d_in[2];
    float* out        = (float*)d_out;

    const int total = NB * IP * JP;      // 16 * 127 * 127 = 258064
    const int block = 256;
    const int grid  = (total + block - 1) / block;
    conv2dcq_kernel<<<grid, block>>>(x, w, bias, out);
}